// round 2
// baseline (speedup 1.0000x reference)
#include <cuda_runtime.h>
#include <stdint.h>

// Problem constants
#define HWp   65536      // 256*256
#define Wp    256
#define Bp    2
#define Jp    512
#define JJp   (Jp*Jp)    // 262144
#define CAPp  16384      // candidate capacity per batch (expected ~7.3k)
#define THp   0.008f
#define J2Lp  10.0f
#define SCALEp 5.0f

// Scratch (static device globals — no allocation allowed)
__device__ float               g_prob[Bp][HWp];
__device__ unsigned long long  g_ckey[Bp][CAPp];
__device__ int                 g_ccnt[Bp];
__device__ int                 g_nvalid[Bp];
__device__ float2              g_juncs[Bp][Jp];

__device__ __forceinline__ float sigf(float x) { return 1.0f / (1.0f + expf(-x)); }

// ---------------------------------------------------------------------------
// K1: junction probability = softmax(raw[:,5:7],axis=1)[:,1]  (max-subtract,
// matching XLA's softmax). Also resets candidate counters for this replay.
// ---------------------------------------------------------------------------
__global__ void k_prob(const float* __restrict__ raw) {
    int p = blockIdx.x * blockDim.x + threadIdx.x;
    int b = blockIdx.y;
    if (p == 0 && b == 0) { g_ccnt[0] = 0; g_ccnt[1] = 0; }
    const float* rb = raw + (size_t)b * 9 * HWp;
    float r5 = rb[5 * HWp + p];
    float r6 = rb[6 * HWp + p];
    float m  = fmaxf(r5, r6);
    float e5 = expf(r5 - m);
    float e6 = expf(r6 - m);
    g_prob[b][p] = e6 / (e5 + e6);
}

// ---------------------------------------------------------------------------
// K2: 3x3 maxpool NMS + threshold; append survivors as sortable 64-bit keys.
// key = (~float_bits(score) << 32) | pixel  -> ascending sort == score desc,
// ties broken by smaller pixel index (matches jax.lax.top_k ordering).
// ---------------------------------------------------------------------------
__global__ void k_cand() {
    int p = blockIdx.x * blockDim.x + threadIdx.x;
    int b = blockIdx.y;
    float a = g_prob[b][p];
    if (a <= THp) return;                 // can never be a valid junction
    int y = p >> 8, x = p & 255;
    float mx = -1.0f;
    #pragma unroll
    for (int dy = -1; dy <= 1; dy++) {
        int ny = y + dy;
        if ((unsigned)ny >= (unsigned)Wp) continue;
        #pragma unroll
        for (int dx = -1; dx <= 1; dx++) {
            if (dx == 0 && dy == 0) continue;
            int nx = x + dx;
            if ((unsigned)nx >= (unsigned)Wp) continue;
            mx = fmaxf(mx, g_prob[b][(ny << 8) + nx]);
        }
    }
    if (a >= mx) {   // a == maxpool(a) semantics (self always in window)
        int pos = atomicAdd(&g_ccnt[b], 1);
        if (pos < CAPp) {
            unsigned inv = ~__float_as_uint(a);
            g_ckey[b][pos] = (((unsigned long long)inv) << 32) | (unsigned)p;
        }
    }
}

// ---------------------------------------------------------------------------
// K3: one block per batch: bitonic sort CAPp keys in smem, take top Jp,
// compute junction coordinates with joff = sigmoid(raw[:,7:9]) - 0.5.
// ---------------------------------------------------------------------------
__global__ void __launch_bounds__(1024) k_topk(const float* __restrict__ raw) {
    extern __shared__ unsigned long long sk[];   // CAPp entries (128 KB)
    int b = blockIdx.x;
    int cnt = g_ccnt[b];
    if (cnt > CAPp) cnt = CAPp;

    for (int i = threadIdx.x; i < CAPp; i += blockDim.x)
        sk[i] = (i < cnt) ? g_ckey[b][i] : ~0ULL;
    __syncthreads();

    // Bitonic sort ascending (key asc == score desc, index asc on ties)
    for (int k = 2; k <= CAPp; k <<= 1) {
        for (int j = k >> 1; j > 0; j >>= 1) {
            for (int t = threadIdx.x; t < CAPp; t += blockDim.x) {
                int ixj = t ^ j;
                if (ixj > t) {
                    bool up = ((t & k) == 0);
                    unsigned long long va = sk[t], vb = sk[ixj];
                    if ((va > vb) == up) { sk[t] = vb; sk[ixj] = va; }
                }
            }
            __syncthreads();
        }
    }

    int nv = cnt < Jp ? cnt : Jp;
    if (threadIdx.x == 0) g_nvalid[b] = nv;
    const float* rb = raw + (size_t)b * 9 * HWp;
    for (int j = threadIdx.x; j < Jp; j += blockDim.x) {
        float2 q = make_float2(0.0f, 0.0f);
        if (j < nv) {
            unsigned long long key = sk[j];
            int p  = (int)(key & 0xFFFFFFFFu);
            int py = p >> 8;
            int px = p & 255;
            float offx = sigf(rb[7 * HWp + p]) - 0.5f;
            float offy = sigf(rb[8 * HWp + p]) - 0.5f;
            q.x = (float)px + offx + 0.5f;
            q.y = (float)py + offy + 0.5f;
        }
        g_juncs[b][j] = q;
    }
}

// ---------------------------------------------------------------------------
// K4: zero counts + support_sum regions (vectorized)
// ---------------------------------------------------------------------------
__global__ void k_zero(float4* __restrict__ dst, int n4) {
    int i = blockIdx.x * blockDim.x + threadIdx.x;
    if (i < n4) dst[i] = make_float4(0.0f, 0.0f, 0.0f, 0.0f);
}

// ---------------------------------------------------------------------------
// K5: decode line per pixel, match endpoints to nearest valid junction
// (argmin with strict-< => first index on ties, ascending j, same as jnp
// argmin), scatter into pair buckets.
// ---------------------------------------------------------------------------
__global__ void __launch_bounds__(256) k_match(const float* __restrict__ raw,
                                               float* __restrict__ counts,
                                               float* __restrict__ support) {
    __shared__ float2 sj[Jp];
    __shared__ int snv;
    int b = blockIdx.y;
    int p = blockIdx.x * blockDim.x + threadIdx.x;

    for (int j = threadIdx.x; j < Jp; j += blockDim.x) sj[j] = g_juncs[b][j];
    if (threadIdx.x == 0) snv = g_nvalid[b];
    __syncthreads();

    const float* rb = raw + (size_t)b * 9 * HWp;
    float r0 = rb[p];
    float r1 = rb[HWp + p];
    float r2 = rb[2 * HWp + p];
    float r3 = rb[3 * HWp + p];

    float md0 = sigf(r0), md1 = sigf(r1), md2 = sigf(r2);
    float d   = sigf(r3);                       // in (0,1); clip is a no-op
    float theta = (md0 - 0.5f) * 6.28318530717958647692f;
    float cs = cosf(theta), ss = sinf(theta);
    float yst = tanf(md1 * 1.57079632679489661923f);
    float yed = tanf(-md2 * 1.57079632679489661923f);
    float ds = d * SCALEp;
    float x0 = (float)(p & 255);
    float y0 = (float)(p >> 8);
    float l0 = fminf(fmaxf((cs - ss * yst) * ds + x0, 0.0f), 255.0f);
    float l1 = fminf(fmaxf((ss + cs * yst) * ds + y0, 0.0f), 255.0f);
    float l2 = fminf(fmaxf((cs - ss * yed) * ds + x0, 0.0f), 255.0f);
    float l3 = fminf(fmaxf((ss + cs * yed) * ds + y0, 0.0f), 255.0f);

    float bd1 = 1e30f, bd2 = 1e30f;
    int   bi1 = 0,     bi2 = 0;
    int nv = snv;
    #pragma unroll 8
    for (int j = 0; j < nv; j++) {
        float2 q = sj[j];                        // smem broadcast, conflict-free
        float dx = l0 - q.x, dy = l1 - q.y;
        float d1 = fmaf(dy, dy, dx * dx);
        float ex = l2 - q.x, ey = l3 - q.y;
        float d2 = fmaf(ey, ey, ex * ex);
        if (d1 < bd1) { bd1 = d1; bi1 = j; }
        if (d2 < bd2) { bd2 = d2; bi2 = j; }
    }

    if (bd1 < J2Lp && bd2 < J2Lp && bi1 != bi2) {
        int imin = min(bi1, bi2), imax = max(bi1, bi2);
        int g = b * JJp + imin * Jp + imax;
        atomicAdd(&counts[g], 1.0f);
        atomicAdd(&support[(size_t)g * 4 + 0], l0);
        atomicAdd(&support[(size_t)g * 4 + 1], l1);
        atomicAdd(&support[(size_t)g * 4 + 2], l2);
        atomicAdd(&support[(size_t)g * 4 + 3], l3);
    }
}

// ---------------------------------------------------------------------------
// K6: lines_adj = (junc[i], junc[j]) masked by counts>0; writes every entry.
// ---------------------------------------------------------------------------
__global__ void k_adj(const float* __restrict__ counts, float4* __restrict__ out) {
    int pid = blockIdx.x * blockDim.x + threadIdx.x;   // 0 .. Bp*JJp-1
    int b = pid >> 18;                                  // JJp = 2^18
    int q = pid & (JJp - 1);
    float c = counts[pid];
    float4 v = make_float4(0.0f, 0.0f, 0.0f, 0.0f);
    if (c > 0.0f) {
        float2 A  = g_juncs[b][q >> 9];
        float2 Bq = g_juncs[b][q & (Jp - 1)];
        v = make_float4(A.x, A.y, Bq.x, Bq.y);
    }
    out[pid] = v;
}

// ---------------------------------------------------------------------------
// Launch. Output layout: lines_adj [B*JJ*4] | counts [B*JJ] | support [B*JJ*4]
// ---------------------------------------------------------------------------
extern "C" void kernel_launch(void* const* d_in, const int* in_sizes, int n_in,
                              void* d_out, int out_size) {
    const float* raw = (const float*)d_in[0];
    float* out = (float*)d_out;
    float* counts  = out + (size_t)Bp * JJp * 4;
    float* support = counts + (size_t)Bp * JJp;

    cudaFuncSetAttribute(k_topk, cudaFuncAttributeMaxDynamicSharedMemorySize,
                         CAPp * (int)sizeof(unsigned long long));

    dim3 gpix(HWp / 256, Bp);
    k_prob<<<gpix, 256>>>(raw);
    k_cand<<<gpix, 256>>>();
    k_topk<<<Bp, 1024, CAPp * sizeof(unsigned long long)>>>(raw);

    int zn4 = (Bp * JJp * 5) / 4;   // counts + support region, float4 granularity
    k_zero<<<(zn4 + 255) / 256, 256>>>((float4*)counts, zn4);

    k_match<<<gpix, 256>>>(raw, counts, support);
    k_adj<<<(Bp * JJp) / 256, 256>>>(counts, (float4*)out);
}

// round 3
// speedup vs baseline: 5.2836x; 5.2836x over previous
#include <cuda_runtime.h>
#include <stdint.h>

// Problem constants
#define HWp   65536      // 256*256
#define Bp    2
#define Jp    512
#define JJp   (Jp*Jp)    // 262144
#define CAPp  16384      // candidate capacity per batch (expected ~7.3k)
#define THp   0.008f
#define J2Lp  10.0f
#define SCALEp 5.0f
#define NBINS 4096       // histogram bins over key top-12 bits
#define SELC  2048       // compaction capacity (>= 512 + max bin pop)
#define RADp  3.16227766f // sqrt(10): max distance that can ever match
#define ZERO4 ((Bp*JJp*5)/4)  // float4 count of counts+support region
#define ZBLK  1280            // zeroing blocks per batch row

// Scratch (static device globals — no allocation allowed)
__device__ float               g_prob[Bp][HWp];
__device__ unsigned long long  g_ckey[Bp][CAPp];
__device__ int                 g_ccnt[Bp];
__device__ int                 g_nvalid[Bp];
__device__ float2              g_juncs[Bp][Jp];
__device__ int                 g_cellStart[Bp][1025];  // CSR over 32x32 cells of 8px
__device__ float2              g_gpos[Bp][Jp];         // junction pos in cell order
__device__ int                 g_gidx[Bp][Jp];         // original top-k index

__device__ __forceinline__ float sigf(float x) { return 1.0f / (1.0f + expf(-x)); }

// ---------------------------------------------------------------------------
// K1: junction probability = softmax(raw[:,5:7],axis=1)[:,1] (max-subtract),
// fused with zeroing of the counts+support output region and counter reset.
// Grid: (256 + ZBLK, Bp) x 256 threads.
// ---------------------------------------------------------------------------
__global__ void k_prob_zero(const float* __restrict__ raw, float4* __restrict__ zdst) {
    int b = blockIdx.y;
    if (blockIdx.x >= 256) {
        int zi = ((blockIdx.x - 256) + b * ZBLK) * 256 + threadIdx.x;
        if (zi < ZERO4) zdst[zi] = make_float4(0.f, 0.f, 0.f, 0.f);
        return;
    }
    int p = blockIdx.x * 256 + threadIdx.x;
    if (p == 0 && b == 0) { g_ccnt[0] = 0; g_ccnt[1] = 0; }
    const float* rb = raw + (size_t)b * 9 * HWp;
    float r5 = rb[5 * HWp + p];
    float r6 = rb[6 * HWp + p];
    float m  = fmaxf(r5, r6);
    float e5 = expf(r5 - m);
    float e6 = expf(r6 - m);
    g_prob[b][p] = e6 / (e5 + e6);
}

// ---------------------------------------------------------------------------
// K2: 3x3 maxpool NMS + threshold; append survivors as sortable 64-bit keys.
// key = (~float_bits(score) << 32) | pixel -> ascending == score desc,
// pixel-index asc on ties (matches jax.lax.top_k ordering).
// ---------------------------------------------------------------------------
__global__ void k_cand() {
    int p = blockIdx.x * blockDim.x + threadIdx.x;
    int b = blockIdx.y;
    float a = g_prob[b][p];
    if (a <= THp) return;
    int y = p >> 8, x = p & 255;
    float mx = -1.0f;
    #pragma unroll
    for (int dy = -1; dy <= 1; dy++) {
        int ny = y + dy;
        if ((unsigned)ny >= 256u) continue;
        #pragma unroll
        for (int dx = -1; dx <= 1; dx++) {
            if (dx == 0 && dy == 0) continue;
            int nx = x + dx;
            if ((unsigned)nx >= 256u) continue;
            mx = fmaxf(mx, g_prob[b][(ny << 8) + nx]);
        }
    }
    if (a >= mx) {
        int pos = atomicAdd(&g_ccnt[b], 1);
        if (pos < CAPp) {
            unsigned inv = ~__float_as_uint(a);
            g_ckey[b][pos] = (((unsigned long long)inv) << 32) | (unsigned)p;
        }
    }
}

// ---------------------------------------------------------------------------
// K3: histogram-select top-512, sort only the selected subset, decode junction
// coordinates, and build the CSR spatial grid. One block per batch.
// ---------------------------------------------------------------------------
struct SmemT {
    union {
        int hist[NBINS];                 // phase 1: histogram/scan
        struct {                         // phase 2: cell grid build
            int cnt1[1024];              // cell counts, then fill cursors
        } c;
    } u;
    unsigned long long sel[SELC];
    int warpsum[32];
    int sT, sCum, sSel;
};

__global__ void __launch_bounds__(1024) k_topk(const float* __restrict__ raw) {
    __shared__ SmemT sm;
    int b = blockIdx.x;
    int tid = threadIdx.x;
    int lane = tid & 31, wid = tid >> 5;
    int cnt = min(g_ccnt[b], CAPp);
    int target = min(Jp, cnt);

    if (cnt == 0) {   // defensive; never hit with this data
        if (tid < Jp) g_juncs[b][tid] = make_float2(0.f, 0.f);
        if (tid <= 1024) g_cellStart[b][tid] = 0;
        if (tid == 0) g_nvalid[b] = 0;
        return;
    }

    // --- histogram over key top-12 bits ---
    for (int i = tid; i < NBINS; i += 1024) sm.u.hist[i] = 0;
    __syncthreads();
    for (int i = tid; i < cnt; i += 1024)
        atomicAdd(&sm.u.hist[(int)(g_ckey[b][i] >> 52)], 1);
    __syncthreads();

    // --- block scan (4 bins/thread) to find threshold bin T ---
    int base = tid * 4;
    int h0 = sm.u.hist[base], h1 = sm.u.hist[base+1];
    int h2 = sm.u.hist[base+2], h3 = sm.u.hist[base+3];
    int tot = h0 + h1 + h2 + h3;
    int inc = tot;
    #pragma unroll
    for (int d = 1; d < 32; d <<= 1) {
        int n = __shfl_up_sync(0xffffffffu, inc, d);
        if (lane >= d) inc += n;
    }
    if (lane == 31) sm.warpsum[wid] = inc;
    __syncthreads();
    if (wid == 0) {
        int v = sm.warpsum[lane];
        int i2 = v;
        #pragma unroll
        for (int d = 1; d < 32; d <<= 1) {
            int n = __shfl_up_sync(0xffffffffu, i2, d);
            if (lane >= d) i2 += n;
        }
        sm.warpsum[lane] = i2 - v;   // exclusive warp offsets
    }
    if (tid == 0) sm.sSel = 0;
    __syncthreads();
    {
        int run = sm.warpsum[wid] + inc - tot;   // exclusive prefix for this thread
        int hh[4] = {h0, h1, h2, h3};
        #pragma unroll
        for (int i = 0; i < 4; i++) {
            run += hh[i];
            if (run >= target && run - hh[i] < target) { sm.sT = base + i; sm.sCum = run; }
        }
    }
    __syncthreads();
    int T = sm.sT;
    int selTotal = min(sm.sCum, SELC);

    // --- compact keys with bin <= T (superset of the 512 smallest keys) ---
    for (int i = tid; i < cnt; i += 1024) {
        unsigned long long key = g_ckey[b][i];
        if ((int)(key >> 52) <= T) {
            int pos = atomicAdd(&sm.sSel, 1);
            if (pos < SELC) sm.sel[pos] = key;
        }
    }
    __syncthreads();

    // --- bitonic sort of M = next_pow2(selTotal) entries (512..2048) ---
    int M = 512;
    while (M < selTotal) M <<= 1;
    for (int i = tid; i < M; i += 1024)
        if (i >= selTotal) sm.sel[i] = ~0ULL;
    __syncthreads();
    for (int k = 2; k <= M; k <<= 1) {
        for (int j = k >> 1; j > 0; j >>= 1) {
            for (int t = tid; t < M; t += 1024) {
                int ixj = t ^ j;
                if (ixj > t) {
                    unsigned long long a = sm.sel[t], c2 = sm.sel[ixj];
                    bool up = ((t & k) == 0);
                    if ((a > c2) == up) { sm.sel[t] = c2; sm.sel[ixj] = a; }
                }
            }
            __syncthreads();
        }
    }

    int nv = target;
    if (tid == 0) g_nvalid[b] = nv;

    // --- decode junction tid (one thread per junction) ---
    float qx = 0.f, qy = 0.f;
    int myCell = -1;
    const float* rb = raw + (size_t)b * 9 * HWp;
    if (tid < Jp) {
        if (tid < nv) {
            unsigned long long key = sm.sel[tid];
            int p = (int)(key & 0xFFFFFFFFu);
            float offx = sigf(rb[7 * HWp + p]) - 0.5f;
            float offy = sigf(rb[8 * HWp + p]) - 0.5f;
            qx = (float)(p & 255) + offx + 0.5f;
            qy = (float)(p >> 8) + offy + 0.5f;
            myCell = (((int)qy >> 3) << 5) + ((int)qx >> 3);   // 32x32 cells of 8px
        }
        g_juncs[b][tid] = make_float2(qx, qy);
    }
    __syncthreads();          // done with hist region before reuse

    // --- build CSR cell grid ---
    sm.u.c.cnt1[tid] = 0;
    __syncthreads();
    if (myCell >= 0) atomicAdd(&sm.u.c.cnt1[myCell], 1);
    __syncthreads();
    int v = sm.u.c.cnt1[tid];
    int inc2 = v;
    #pragma unroll
    for (int d = 1; d < 32; d <<= 1) {
        int n = __shfl_up_sync(0xffffffffu, inc2, d);
        if (lane >= d) inc2 += n;
    }
    if (lane == 31) sm.warpsum[wid] = inc2;
    __syncthreads();
    if (wid == 0) {
        int vv = sm.warpsum[lane];
        int i2 = vv;
        #pragma unroll
        for (int d = 1; d < 32; d <<= 1) {
            int n = __shfl_up_sync(0xffffffffu, i2, d);
            if (lane >= d) i2 += n;
        }
        sm.warpsum[lane] = i2 - vv;
    }
    __syncthreads();
    int excl = sm.warpsum[wid] + inc2 - v;
    g_cellStart[b][tid] = excl;
    if (tid == 1023) g_cellStart[b][1024] = excl + v;   // == nv
    __syncthreads();
    sm.u.c.cnt1[tid] = excl;     // fill cursors
    __syncthreads();
    if (myCell >= 0) {
        int pos = atomicAdd(&sm.u.c.cnt1[myCell], 1);
        g_gpos[b][pos] = make_float2(qx, qy);
        g_gidx[b][pos] = tid;
    }
}

// ---------------------------------------------------------------------------
// Pruned nearest-junction search: any junction with d^2 < 10 lies within a
// 2x2 window of 8px cells around the endpoint. (d, idx) lexicographic min
// reproduces the reference argmin first-index tie-break exactly.
// ---------------------------------------------------------------------------
__device__ __forceinline__ void nearest(int b, float ex, float ey,
                                        float& bd, int& bi) {
    int cx0 = ((int)fmaxf(ex - RADp, 0.0f)) >> 3;
    int cx1 = ((int)fminf(ex + RADp, 255.0f)) >> 3;
    int cy0 = ((int)fmaxf(ey - RADp, 0.0f)) >> 3;
    int cy1 = ((int)fminf(ey + RADp, 255.0f)) >> 3;
    for (int cy = cy0; cy <= cy1; cy++) {
        for (int cx = cx0; cx <= cx1; cx++) {
            int c = (cy << 5) + cx;
            int s = __ldg(&g_cellStart[b][c]);
            int e = __ldg(&g_cellStart[b][c + 1]);
            for (int k = s; k < e; k++) {
                float2 q = __ldg(&g_gpos[b][k]);
                int idx  = __ldg(&g_gidx[b][k]);
                float dx = ex - q.x, dy = ey - q.y;
                float d = fmaf(dy, dy, dx * dx);
                if (d < bd || (d == bd && idx < bi)) { bd = d; bi = idx; }
            }
        }
    }
}

// ---------------------------------------------------------------------------
// K4: decode line per pixel, match endpoints via the spatial grid, scatter.
// ---------------------------------------------------------------------------
__global__ void __launch_bounds__(256) k_match(const float* __restrict__ raw,
                                               float* __restrict__ counts,
                                               float* __restrict__ support) {
    int b = blockIdx.y;
    int p = blockIdx.x * 256 + threadIdx.x;

    const float* rb = raw + (size_t)b * 9 * HWp;
    float r0 = rb[p];
    float r1 = rb[HWp + p];
    float r2 = rb[2 * HWp + p];
    float r3 = rb[3 * HWp + p];

    float md0 = sigf(r0), md1 = sigf(r1), md2 = sigf(r2);
    float d   = sigf(r3);
    float theta = (md0 - 0.5f) * 6.28318530717958647692f;
    float cs = cosf(theta), ss = sinf(theta);
    float yst = tanf(md1 * 1.57079632679489661923f);
    float yed = tanf(-md2 * 1.57079632679489661923f);
    float ds = d * SCALEp;
    float x0 = (float)(p & 255);
    float y0 = (float)(p >> 8);
    float l0 = fminf(fmaxf((cs - ss * yst) * ds + x0, 0.0f), 255.0f);
    float l1 = fminf(fmaxf((ss + cs * yst) * ds + y0, 0.0f), 255.0f);
    float l2 = fminf(fmaxf((cs - ss * yed) * ds + x0, 0.0f), 255.0f);
    float l3 = fminf(fmaxf((ss + cs * yed) * ds + y0, 0.0f), 255.0f);

    float bd1 = 1e30f, bd2 = 1e30f;
    int   bi1 = Jp,    bi2 = Jp;
    nearest(b, l0, l1, bd1, bi1);
    nearest(b, l2, l3, bd2, bi2);

    if (bd1 < J2Lp && bd2 < J2Lp && bi1 != bi2) {
        int imin = min(bi1, bi2), imax = max(bi1, bi2);
        int g = b * JJp + imin * Jp + imax;
        atomicAdd(&counts[g], 1.0f);
        atomicAdd(&support[(size_t)g * 4 + 0], l0);
        atomicAdd(&support[(size_t)g * 4 + 1], l1);
        atomicAdd(&support[(size_t)g * 4 + 2], l2);
        atomicAdd(&support[(size_t)g * 4 + 3], l3);
    }
}

// ---------------------------------------------------------------------------
// K5: lines_adj = (junc[i], junc[j]) masked by counts>0; writes every entry.
// ---------------------------------------------------------------------------
__global__ void k_adj(const float* __restrict__ counts, float4* __restrict__ out) {
    int pid = blockIdx.x * blockDim.x + threadIdx.x;   // 0 .. Bp*JJp-1
    int b = pid >> 18;                                  // JJp = 2^18
    int q = pid & (JJp - 1);
    float c = counts[pid];
    float4 v = make_float4(0.f, 0.f, 0.f, 0.f);
    if (c > 0.0f) {
        float2 A  = g_juncs[b][q >> 9];
        float2 Bq = g_juncs[b][q & (Jp - 1)];
        v = make_float4(A.x, A.y, Bq.x, Bq.y);
    }
    out[pid] = v;
}

// ---------------------------------------------------------------------------
// Launch. Output layout: lines_adj [B*JJ*4] | counts [B*JJ] | support [B*JJ*4]
// ---------------------------------------------------------------------------
extern "C" void kernel_launch(void* const* d_in, const int* in_sizes, int n_in,
                              void* d_out, int out_size) {
    const float* raw = (const float*)d_in[0];
    float* out = (float*)d_out;
    float* counts  = out + (size_t)Bp * JJp * 4;
    float* support = counts + (size_t)Bp * JJp;

    dim3 gprob(256 + ZBLK, Bp);
    k_prob_zero<<<gprob, 256>>>(raw, (float4*)counts);

    dim3 gpix(HWp / 256, Bp);
    k_cand<<<gpix, 256>>>();
    k_topk<<<Bp, 1024>>>(raw);
    k_match<<<gpix, 256>>>(raw, counts, support);
    k_adj<<<(Bp * JJp) / 256, 256>>>(counts, (float4*)out);
}